// round 6
// baseline (speedup 1.0000x reference)
#include <cuda_runtime.h>

// ProportionalNeuron: leaky-integrate-and-fire scan, one thread per (b,f) neuron.
//   ff  = x[t,b,f] * W[f,f]   (W == 0.4*I exactly -> matmul is bit-exact elementwise)
//   i   = leak_i * i + ff
//   v   = (z ? 0 : leak_v*v) + i       ((1-z) in {0,1} exactly)
//   z   = v > thresh
//
// R5 -> R6: register prefetch ring suffered SASS scoreboard-slot aliasing
// (6 wbar slots shared by 64 LDGs -> effective prefetch distance ~10 steps).
// Replace with an explicit cp.async (LDGSTS) pipeline: SMEM ring of 8 group
// slots x 8 steps x 128B, cp.async.commit_group per 8 steps, wait_group 6
// gives a guaranteed 56-step (~1100 cyc) prefetch distance. Warp count stays
// 1024 (max scheduler coverage). Arithmetic bit-identical.

#define T_STEPS 2048
#define B_DIM   64
#define F_DIM   512
#define N_NEUR  (B_DIM * F_DIM)   // 32768 -> 131072 B per time step
#define GRP     8                 // steps per commit group
#define NSLOT   8                 // group slots in the SMEM ring (7 in flight + 1 consuming)

__global__ __launch_bounds__(32, 8)
void snn_scan_kernel(const float* __restrict__ x,
                     const float* __restrict__ W,
                     const float* __restrict__ leak_i,
                     const float* __restrict__ leak_v,
                     const float* __restrict__ thresh,
                     float* __restrict__ out)
{
    __shared__ float buf[NSLOT * GRP * 32];   // 8 KB: [slot][step][lane]

    const int lane = threadIdx.x;
    const int n = blockIdx.x * 32 + lane;     // 0..32767
    const int f = n & (F_DIM - 1);

    // Diagonal of W (off-diagonal contributions of x@W.T are exactly 0)
    const float wff = W[f * F_DIM + f];
    const float li  = leak_i[f];
    const float lv  = leak_v[f];
    const float th  = thresh[f];

    const unsigned sbase = (unsigned)__cvta_generic_to_shared(buf) + lane * 4u;

    // Prologue: fill 7 groups (steps 0..55)
#pragma unroll
    for (int g = 0; g < NSLOT - 1; ++g) {
        const float* gp = x + g * GRP * N_NEUR + n;
#pragma unroll
        for (int k = 0; k < GRP; ++k) {
            asm volatile("cp.async.ca.shared.global [%0], [%1], 4;\n"
                         :: "r"(sbase + (unsigned)((g * GRP + k) * 128)),
                            "l"(gp + k * N_NEUR));
        }
        asm volatile("cp.async.commit_group;\n" ::: "memory");
    }

    float i_s = 0.0f;
    float v_s = 0.0f;
    bool  zb  = false;

    for (int t = 0; t < T_STEPS; t += GRP) {
        // Wait until the group for steps t..t+7 (committed 7 groups ago) is done.
        asm volatile("cp.async.wait_group 6;\n" ::: "memory");

        const int cg = (t >> 3) & (NSLOT - 1);   // slot being consumed

        // Batch-load this group's 8 values from SMEM (conflict-free: lane -> bank)
        float xr[GRP];
#pragma unroll
        for (int k = 0; k < GRP; ++k)
            xr[k] = buf[(cg * GRP + k) * 32 + lane];

        // Issue prefetch for steps t+56..t+63 into slot (cg+7)&7.
        // Always commit (possibly empty) to keep wait_group accounting uniform.
        if (t + (NSLOT - 1) * GRP < T_STEPS) {
            const float* gp = x + (t + (NSLOT - 1) * GRP) * N_NEUR + n;
            const int ps = (cg + NSLOT - 1) & (NSLOT - 1);
#pragma unroll
            for (int k = 0; k < GRP; ++k) {
                asm volatile("cp.async.ca.shared.global [%0], [%1], 4;\n"
                             :: "r"(sbase + (unsigned)((ps * GRP + k) * 128)),
                                "l"(gp + k * N_NEUR));
            }
        }
        asm volatile("cp.async.commit_group;\n" ::: "memory");

        // Compute and store 8 steps
        float* op = out + t * N_NEUR + n;
#pragma unroll
        for (int k = 0; k < GRP; ++k) {
            const float ff  = __fmul_rn(xr[k], wff);
            i_s = __fadd_rn(__fmul_rn(li, i_s), ff);
            const float lvv = __fmul_rn(lv, v_s);
            v_s = __fadd_rn(zb ? 0.0f : lvv, i_s);
            zb  = (v_s > th);
            __stcs(op + k * N_NEUR, zb ? 1.0f : 0.0f);
        }
    }
}

extern "C" void kernel_launch(void* const* d_in, const int* in_sizes, int n_in,
                              void* d_out, int out_size)
{
    const float* x      = (const float*)d_in[0];
    const float* W      = (const float*)d_in[1];
    const float* leak_i = (const float*)d_in[2];
    const float* leak_v = (const float*)d_in[3];
    const float* thresh = (const float*)d_in[4];
    float* out = (float*)d_out;

    const int block = 32;
    const int grid  = N_NEUR / block;   // 1024 blocks, 1024 warps
    snn_scan_kernel<<<grid, block>>>(x, W, leak_i, leak_v, thresh, out);
}